// round 3
// baseline (speedup 1.0000x reference)
#include <cuda_runtime.h>
#include <cuda_bf16.h>
#include <cstdint>

// Problem constants (fixed by setup_inputs)
#define HPM       8
#define NUM_PAGES 4096
#define PAGE_SIZE 16
#define DPM       128
#define MAX_SEQS  8
#define MAX_PPS   256
#define D4        (DPM / 4)                                    // 32 float4 per row
#define PAGES_ELEMS (2LL * HPM * NUM_PAGES * PAGE_SIZE * DPM)  // 134,217,728 floats
#define INNER_F4  (HPM * NUM_PAGES * PAGE_SIZE * D4)           // 1<<24 float4 per tensor
#define TOTAL_F4  (2u * INNER_F4)                              // 1<<25
#define NTHREADS  256
#define F4_PER_BLOCK 1024u
#define NBLOCKS   (TOTAL_F4 / F4_PER_BLOCK)                    // 32768

// Scratch (device globals — no allocation allowed). Zero-initialized at load.
__device__ int      g_blk_of_page[NUM_PAGES];  // -1 => keep old contents, else block index
__device__ int      g_page_of_block[MAX_PPS];
__device__ unsigned g_ready;                   // setup-done flag (reset by last block)
__device__ unsigned g_done;                    // completion counter

__device__ __forceinline__ unsigned ld_acquire(const unsigned* p) {
    unsigned v;
    asm volatile("ld.global.acquire.gpu.u32 %0, [%1];" : "=r"(v) : "l"(p) : "memory");
    return v;
}
__device__ __forceinline__ void st_release(unsigned* p, unsigned v) {
    asm volatile("st.global.release.gpu.u32 [%0], %1;" :: "l"(p), "r"(v) : "memory");
}

// ---------------------------------------------------------------------------
// Fused kernel. Block 0: first-fit allocation scan + small outputs, then
// publishes g_ready. All blocks: spin-acquire g_ready, then assemble their
// 1024-f4 slice of [2, H, P, PS, D]. Last block to finish resets the flags
// so graph replays start clean.
// ---------------------------------------------------------------------------
__global__ void __launch_bounds__(NTHREADS)
fused_pages_kernel(const float4* __restrict__ key,          // [1, S, H, D]
                   const float4* __restrict__ value,
                   const float4* __restrict__ key_pages,    // [H, P, PS, D]
                   const float4* __restrict__ value_pages,
                   const int*    __restrict__ page_indices,
                   const int*    __restrict__ seq_page_indices,
                   const int*    __restrict__ slot_p,
                   const int*    __restrict__ true_length_p,
                   float4* __restrict__ out,                 // [2, H, P, PS, D]
                   float*  __restrict__ out_pi,              // [4096]
                   float*  __restrict__ out_spi)             // [8, 256]
{
    const int tid  = threadIdx.x;
    const int lane = tid & 31;
    const int wrp  = tid >> 5;

    // ---------------- Phase 0: block 0 does setup ----------------
    if (blockIdx.x == 0) {
        __shared__ int s_wsum[8];

        // 16 pages per thread (256 threads x 16 = 4096); page 0 reserved.
        int local[16];
        int cnt = 0;
#pragma unroll
        for (int j = 0; j < 16; j++) {
            int p  = tid * 16 + j;
            int fr = (p >= 1) && (page_indices[p] == 0);
            local[j] = fr;
            cnt += fr;
        }

        // Warp inclusive scan of per-thread counts
        int incl = cnt;
#pragma unroll
        for (int off = 1; off < 32; off <<= 1) {
            int n = __shfl_up_sync(0xffffffffu, incl, off);
            if (lane >= off) incl += n;
        }
        if (lane == 31) s_wsum[wrp] = incl;
        __syncthreads();

        if (wrp == 0 && lane < 8) {
            int v = s_wsum[lane];
            int s = v;
#pragma unroll
            for (int off = 1; off < 8; off <<= 1) {
                int n = __shfl_up_sync(0xffu, s, off);
                if (lane >= off) s += n;
            }
            s_wsum[lane] = s - v;   // exclusive warp base
        }
        __syncthreads();

        const int excl = s_wsum[wrp] + (incl - cnt);

        const int tl = true_length_p[0];
        int nb = (tl + PAGE_SIZE - 1) / PAGE_SIZE;
        if (nb > MAX_PPS) nb = MAX_PPS;

        int run = excl;
#pragma unroll
        for (int j = 0; j < 16; j++) {
            int p = tid * 16 + j;
            int b = -1;
            if (local[j]) {
                if (run < nb) { b = run; g_page_of_block[run] = p; }
                run++;
            }
            g_blk_of_page[p] = b;
            out_pi[p] = (b >= 0) ? 1.0f : (float)page_indices[p];
        }
        __syncthreads();   // g_page_of_block visible block-wide

        // seq_page_indices output (8 x 256)
        const int slot = slot_p[0];
        for (int i = tid; i < MAX_SEQS * MAX_PPS; i += NTHREADS) {
            int r = i >> 8, c = i & 255;
            float v = (float)seq_page_indices[i];
            if (r == slot && c < nb) v = (float)g_page_of_block[c];
            out_spi[i] = v;
        }
        __syncthreads();
        if (tid == 0) {
            __threadfence();            // make all block-0 writes visible GPU-wide
            st_release(&g_ready, 1u);   // publish
        }
        __syncthreads();
    } else {
        // ---------------- Phase 0': everyone else waits ----------------
        if (tid == 0) {
            while (ld_acquire(&g_ready) == 0u) __nanosleep(64);
        }
        __syncthreads();
    }

    // ---------------- Phase 1: assemble this block's 1024-f4 slice ----------------
    const unsigned base = blockIdx.x * F4_PER_BLOCK + tid;
    const unsigned t = base >> 24;                      // 0 = key, 1 = value (block-uniform)
    const float4* __restrict__ kv    = t ? value       : key;
    const float4* __restrict__ pages = t ? value_pages : key_pages;

    const float4* srcs[4];
#pragma unroll
    for (int j = 0; j < 4; j++) {
        unsigned idx = base + j * 256u;
        unsigned v   = idx;
        unsigned d4  = v & (D4 - 1);        v >>= 5;
        unsigned row = v & (PAGE_SIZE - 1); v >>= 4;
        unsigned p   = v & (NUM_PAGES - 1); v >>= 12;
        unsigned h   = v & (HPM - 1);

        int b = g_blk_of_page[p];            // warp-uniform (16KB, L2-resident)
        unsigned s    = (unsigned)b * PAGE_SIZE + row;
        unsigned offA = (s * HPM + h) * D4 + d4;        // key/value (transpose folded)
        unsigned offB = idx & (INNER_F4 - 1);           // pass-through pages
        srcs[j] = (b >= 0) ? (kv + offA) : (pages + offB);
    }

    float4 vals[4];
#pragma unroll
    for (int j = 0; j < 4; j++) vals[j] = __ldg(srcs[j]);   // 4 back-to-back LDG.128

#pragma unroll
    for (int j = 0; j < 4; j++) out[base + j * 256u] = vals[j];

    // ---------------- Epilogue: last block resets flags for next replay ----------------
    __syncthreads();
    if (tid == 0) {
        __threadfence();
        unsigned done = atomicAdd(&g_done, 1u);
        if (done == gridDim.x - 1u) {
            g_done = 0u;
            st_release(&g_ready, 0u);
        }
    }
}

// ---------------------------------------------------------------------------
// Launch — single fused kernel.
// Inputs: key, value, key_pages, value_pages, page_indices, seq_page_indices,
//         slot, true_length
// Output: concat(pages[2,H,P,PS,D], page_indices[4096], seq_page_indices[2048])
// ---------------------------------------------------------------------------
extern "C" void kernel_launch(void* const* d_in, const int* in_sizes, int n_in,
                              void* d_out, int out_size)
{
    const float* key          = (const float*)d_in[0];
    const float* value        = (const float*)d_in[1];
    const float* key_pages    = (const float*)d_in[2];
    const float* value_pages  = (const float*)d_in[3];
    const int*   page_indices = (const int*)d_in[4];
    const int*   seq_page_ind = (const int*)d_in[5];
    const int*   slot         = (const int*)d_in[6];
    const int*   true_length  = (const int*)d_in[7];

    float* out_pages = (float*)d_out;
    float* out_pi    = out_pages + PAGES_ELEMS;
    float* out_spi   = out_pi + NUM_PAGES;

    fused_pages_kernel<<<NBLOCKS, NTHREADS>>>(
        (const float4*)key, (const float4*)value,
        (const float4*)key_pages, (const float4*)value_pages,
        page_indices, seq_page_ind, slot, true_length,
        (float4*)out_pages, out_pi, out_spi);
}